// round 1
// baseline (speedup 1.0000x reference)
#include <cuda_runtime.h>
#include <cstdint>

// ---------------------------------------------------------------------------
// Problem constants
// ---------------------------------------------------------------------------
constexpr int B_   = 16;
constexpr int S_   = 2048;
constexpr int D_   = 128;
constexpr int BQ_  = 64;   // query rows per CTA
constexpr int BK_  = 64;   // key cols per iteration
constexpr int QS_STRIDE = 129;  // padded smem row stride (floats) for Q/K tiles
constexpr int PS_STRIDE = 65;   // padded smem row stride for P tile

// Packed dropout keep-mask: 16*2048*2048 bits = 2^26 bits = 8 MB
__device__ __align__(16) unsigned int g_mask[(1u << 26) / 32];

// ---------------------------------------------------------------------------
// Threefry-2x32 (JAX partitionable path): key=(0,42), counter=(0, idx),
// 32-bit draw = out0 ^ out1.  keep iff uniform(bits) < 1 - dropout_p.
// ---------------------------------------------------------------------------
__device__ __forceinline__ void tf_round(unsigned &x0, unsigned &x1, int r) {
    x0 += x1;
    x1 = __funnelshift_l(x1, x1, r);   // rotl32
    x1 ^= x0;
}

__global__ void __launch_bounds__(256) mask_kernel(const float* __restrict__ p_dropout) {
    const unsigned idx = blockIdx.x * 256u + threadIdx.x;   // element index < 2^26

    const unsigned ks0 = 0u;
    const unsigned ks1 = 42u;
    const unsigned ks2 = 0x1BD11BDAu ^ 0u ^ 42u;

    unsigned x0 = 0u + ks0;       // counter hi = 0
    unsigned x1 = idx + ks1;      // counter lo = idx

    tf_round(x0, x1, 13); tf_round(x0, x1, 15); tf_round(x0, x1, 26); tf_round(x0, x1, 6);
    x0 += ks1; x1 += ks2 + 1u;
    tf_round(x0, x1, 17); tf_round(x0, x1, 29); tf_round(x0, x1, 16); tf_round(x0, x1, 24);
    x0 += ks2; x1 += ks0 + 2u;
    tf_round(x0, x1, 13); tf_round(x0, x1, 15); tf_round(x0, x1, 26); tf_round(x0, x1, 6);
    x0 += ks0; x1 += ks1 + 3u;
    tf_round(x0, x1, 17); tf_round(x0, x1, 29); tf_round(x0, x1, 16); tf_round(x0, x1, 24);
    x0 += ks1; x1 += ks2 + 4u;
    tf_round(x0, x1, 13); tf_round(x0, x1, 15); tf_round(x0, x1, 26); tf_round(x0, x1, 6);
    x0 += ks2; x1 += ks0 + 5u;

    const unsigned bits = x0 ^ x1;

    const float kp = 1.0f - *p_dropout;            // keep_prob, same fp32 arithmetic as ref
    const float u  = __uint_as_float((bits >> 9) | 0x3f800000u) - 1.0f;
    const unsigned ballot = __ballot_sync(0xffffffffu, u < kp);
    if ((threadIdx.x & 31u) == 0u) g_mask[idx >> 5] = ballot;
}

// ---------------------------------------------------------------------------
// Flash attention (fp32) with tensor scale + dropout-on-numerator.
// Grid: (S/BQ, B). 256 threads. Online softmax; Z sums ALL keys (mask only
// gates the P*V numerator, matching the reference).
// ---------------------------------------------------------------------------
__global__ void __launch_bounds__(256, 1) attn_kernel(
    const float* __restrict__ Q, const float* __restrict__ K,
    const float* __restrict__ V, const float* __restrict__ inv_scale,
    const float* __restrict__ p_dropout, float* __restrict__ Out)
{
    extern __shared__ float sm[];
    float* Qs = sm;                         // [64][129]
    float* Ks = Qs + 64 * QS_STRIDE;        // [64][129]
    float* Vs = Ks + 64 * QS_STRIDE;        // [64][128]
    float* Ps = Vs + 64 * D_;               // [64][65]
    float* rs = Ps + 64 * PS_STRIDE;        // [64] reciprocal of inv_scale

    const int b     = blockIdx.y;
    const int qbase = blockIdx.x * BQ_;
    const int tid   = threadIdx.x;
    const int tx    = tid & 15;             // 16 col groups
    const int ty    = tid >> 4;             // 16 row groups

    const float kp = 1.0f - *p_dropout;

    const float* Qb = Q + (size_t)(b * S_ + qbase) * D_;
    const float* Kb = K + (size_t)b * S_ * D_;
    const float* Vb = V + (size_t)b * S_ * D_;

    // Load Q tile (64x128), scalar-store into padded smem
    for (int t = tid; t < 64 * 32; t += 256) {
        const int r = t >> 5, c4 = (t & 31) << 2;
        const float4 q4 = *reinterpret_cast<const float4*>(Qb + r * D_ + c4);
        float* d = Qs + r * QS_STRIDE + c4;
        d[0] = q4.x; d[1] = q4.y; d[2] = q4.z; d[3] = q4.w;
    }
    if (tid < 64) rs[tid] = 1.0f / inv_scale[(size_t)b * S_ + qbase + tid];

    float O[4][8];
    float mrun[4], Zrun[4];
#pragma unroll
    for (int i = 0; i < 4; i++) {
        mrun[i] = -1e30f; Zrun[i] = 0.0f;
#pragma unroll
        for (int v = 0; v < 8; v++) O[i][v] = 0.0f;
    }

    // mask word base per owned row: ((b*S + q) * S) / 32 = (b*S + q) * 64
    unsigned wbase[4];
#pragma unroll
    for (int i = 0; i < 4; i++)
        wbase[i] = (unsigned)(b * S_ + qbase + 4 * ty + i) * (S_ / 32);
    const unsigned shiftbase = (unsigned)(4 * tx) & 31u;
    const unsigned txword    = (unsigned)(tx >> 3);   // (4*tx+j)>>5 within the 64-wide tile

    for (int kb = 0; kb < S_ / BK_; kb++) {
        __syncthreads();
        // Load K and V tiles
        const float* Kt = Kb + (size_t)kb * BK_ * D_;
        const float* Vt = Vb + (size_t)kb * BK_ * D_;
        for (int t = tid; t < 64 * 32; t += 256) {
            const int r = t >> 5, c4 = (t & 31) << 2;
            const float4 k4 = *reinterpret_cast<const float4*>(Kt + r * D_ + c4);
            float* kd = Ks + r * QS_STRIDE + c4;
            kd[0] = k4.x; kd[1] = k4.y; kd[2] = k4.z; kd[3] = k4.w;
            *reinterpret_cast<float4*>(Vs + r * D_ + c4) =
                *reinterpret_cast<const float4*>(Vt + r * D_ + c4);
        }
        __syncthreads();

        // ---- S = Q K^T  (4x4 micro-tile per thread) ----
        float acc[4][4] = {};
        const float* qrow = Qs + 4 * ty * QS_STRIDE;
        const float* krow = Ks + 4 * tx * QS_STRIDE;
#pragma unroll 8
        for (int kk = 0; kk < D_; kk++) {
            const float a0 = qrow[kk];
            const float a1 = qrow[QS_STRIDE + kk];
            const float a2 = qrow[2 * QS_STRIDE + kk];
            const float a3 = qrow[3 * QS_STRIDE + kk];
            const float b0 = krow[kk];
            const float b1 = krow[QS_STRIDE + kk];
            const float b2 = krow[2 * QS_STRIDE + kk];
            const float b3 = krow[3 * QS_STRIDE + kk];
            acc[0][0] += a0 * b0; acc[0][1] += a0 * b1; acc[0][2] += a0 * b2; acc[0][3] += a0 * b3;
            acc[1][0] += a1 * b0; acc[1][1] += a1 * b1; acc[1][2] += a1 * b2; acc[1][3] += a1 * b3;
            acc[2][0] += a2 * b0; acc[2][1] += a2 * b1; acc[2][2] += a2 * b2; acc[2][3] += a2 * b3;
            acc[3][0] += a3 * b0; acc[3][1] += a3 * b1; acc[3][2] += a3 * b2; acc[3][3] += a3 * b3;
        }

        // ---- scale, online softmax, dropout mask, write P tile ----
        const unsigned woff = (unsigned)(kb * 2) + txword;
#pragma unroll
        for (int i = 0; i < 4; i++) {
            const float rsc = rs[4 * ty + i];
            float s0 = acc[i][0] * rsc, s1 = acc[i][1] * rsc;
            float s2 = acc[i][2] * rsc, s3 = acc[i][3] * rsc;

            float mx = fmaxf(fmaxf(s0, s1), fmaxf(s2, s3));
            mx = fmaxf(mx, __shfl_xor_sync(0xffffffffu, mx, 1));
            mx = fmaxf(mx, __shfl_xor_sync(0xffffffffu, mx, 2));
            mx = fmaxf(mx, __shfl_xor_sync(0xffffffffu, mx, 4));
            mx = fmaxf(mx, __shfl_xor_sync(0xffffffffu, mx, 8));

            const float mn    = fmaxf(mrun[i], mx);
            const float alpha = __expf(mrun[i] - mn);
            mrun[i] = mn;

            float p0 = __expf(s0 - mn), p1 = __expf(s1 - mn);
            float p2 = __expf(s2 - mn), p3 = __expf(s3 - mn);
            float rsum = (p0 + p1) + (p2 + p3);
            rsum += __shfl_xor_sync(0xffffffffu, rsum, 1);
            rsum += __shfl_xor_sync(0xffffffffu, rsum, 2);
            rsum += __shfl_xor_sync(0xffffffffu, rsum, 4);
            rsum += __shfl_xor_sync(0xffffffffu, rsum, 8);
            Zrun[i] = Zrun[i] * alpha + rsum;

#pragma unroll
            for (int v = 0; v < 8; v++) O[i][v] *= alpha;

            const unsigned mword = g_mask[wbase[i] + woff];
            if (!((mword >> (shiftbase + 0u)) & 1u)) p0 = 0.0f;
            if (!((mword >> (shiftbase + 1u)) & 1u)) p1 = 0.0f;
            if (!((mword >> (shiftbase + 2u)) & 1u)) p2 = 0.0f;
            if (!((mword >> (shiftbase + 3u)) & 1u)) p3 = 0.0f;

            float* prow = Ps + (4 * ty + i) * PS_STRIDE + 4 * tx;
            prow[0] = p0; prow[1] = p1; prow[2] = p2; prow[3] = p3;
        }
        __syncthreads();

        // ---- O += P * V  (4x8 micro-tile per thread) ----
        const float* prow0 = Ps + 4 * ty * PS_STRIDE;
#pragma unroll 4
        for (int c = 0; c < BK_; c++) {
            const float a0 = prow0[c];
            const float a1 = prow0[PS_STRIDE + c];
            const float a2 = prow0[2 * PS_STRIDE + c];
            const float a3 = prow0[3 * PS_STRIDE + c];
            const float4 v0 = *reinterpret_cast<const float4*>(Vs + c * D_ + 8 * tx);
            const float4 v1 = *reinterpret_cast<const float4*>(Vs + c * D_ + 8 * tx + 4);
            O[0][0] += a0 * v0.x; O[0][1] += a0 * v0.y; O[0][2] += a0 * v0.z; O[0][3] += a0 * v0.w;
            O[0][4] += a0 * v1.x; O[0][5] += a0 * v1.y; O[0][6] += a0 * v1.z; O[0][7] += a0 * v1.w;
            O[1][0] += a1 * v0.x; O[1][1] += a1 * v0.y; O[1][2] += a1 * v0.z; O[1][3] += a1 * v0.w;
            O[1][4] += a1 * v1.x; O[1][5] += a1 * v1.y; O[1][6] += a1 * v1.z; O[1][7] += a1 * v1.w;
            O[2][0] += a2 * v0.x; O[2][1] += a2 * v0.y; O[2][2] += a2 * v0.z; O[2][3] += a2 * v0.w;
            O[2][4] += a2 * v1.x; O[2][5] += a2 * v1.y; O[2][6] += a2 * v1.z; O[2][7] += a2 * v1.w;
            O[3][0] += a3 * v0.x; O[3][1] += a3 * v0.y; O[3][2] += a3 * v0.z; O[3][3] += a3 * v0.w;
            O[3][4] += a3 * v1.x; O[3][5] += a3 * v1.y; O[3][6] += a3 * v1.z; O[3][7] += a3 * v1.w;
        }
    }

    // ---- epilogue: out = O / (Z * keep_prob) ----
#pragma unroll
    for (int i = 0; i < 4; i++) {
        const float inv = 1.0f / (Zrun[i] * kp);
        float* orow = Out + (size_t)(b * S_ + qbase + 4 * ty + i) * D_ + 8 * tx;
        float4 o0 = make_float4(O[i][0] * inv, O[i][1] * inv, O[i][2] * inv, O[i][3] * inv);
        float4 o1 = make_float4(O[i][4] * inv, O[i][5] * inv, O[i][6] * inv, O[i][7] * inv);
        *reinterpret_cast<float4*>(orow)     = o0;
        *reinterpret_cast<float4*>(orow + 4) = o1;
    }
}

// ---------------------------------------------------------------------------
// Launch
// ---------------------------------------------------------------------------
extern "C" void kernel_launch(void* const* d_in, const int* in_sizes, int n_in,
                              void* d_out, int out_size) {
    const float* Q   = (const float*)d_in[0];
    const float* K   = (const float*)d_in[1];
    const float* V   = (const float*)d_in[2];
    const float* isf = (const float*)d_in[3];
    const float* dp  = (const float*)d_in[4];
    float* Out = (float*)d_out;

    constexpr int SMEM_BYTES =
        (64 * QS_STRIDE * 2 + 64 * D_ + 64 * PS_STRIDE + 64) * (int)sizeof(float);
    cudaFuncSetAttribute(attn_kernel,
                         cudaFuncAttributeMaxDynamicSharedMemorySize, SMEM_BYTES);

    // 1) regenerate JAX-exact dropout keep-mask (packed bits)
    mask_kernel<<<(1u << 26) / 256, 256>>>(dp);

    // 2) fused flash attention
    dim3 grid(S_ / BQ_, B_);
    attn_kernel<<<grid, 256, SMEM_BYTES>>>(Q, K, V, isf, dp, Out);
}

// round 2
// speedup vs baseline: 1.2981x; 1.2981x over previous
#include <cuda_runtime.h>
#include <cstdint>

typedef unsigned long long ull;

// ---------------------------------------------------------------------------
// Problem constants
// ---------------------------------------------------------------------------
constexpr int B_ = 16, S_ = 2048, D_ = 128;
constexpr int BQ = 128, BK = 128;
constexpr int QSTR = 132;           // Qs row stride (float4 aligned)
constexpr int KSTR = 130;           // Kt / P row stride (float2 aligned)
constexpr int NIT  = S_ / BK;       // 16

// Packed dropout keep-mask: 16*2048*2048 bits = 8 MB
__device__ __align__(16) unsigned int g_mask[(1u << 26) / 32];

// ---------------------------------------------------------------------------
// Threefry-2x32 (JAX partitionable): key=(0,42), ctr=(0,idx), draw = x0^x1
// ---------------------------------------------------------------------------
__device__ __forceinline__ void tf_round(unsigned &x0, unsigned &x1, int r) {
    x0 += x1;
    x1 = __funnelshift_l(x1, x1, r);
    x1 ^= x0;
}

__global__ void __launch_bounds__(256) mask_kernel(const float* __restrict__ p_dropout) {
    const unsigned idx = blockIdx.x * 256u + threadIdx.x;
    const unsigned ks0 = 0u, ks1 = 42u, ks2 = 0x1BD11BDAu ^ 42u;
    unsigned x0 = ks0, x1 = idx + ks1;
    tf_round(x0,x1,13); tf_round(x0,x1,15); tf_round(x0,x1,26); tf_round(x0,x1,6);
    x0 += ks1; x1 += ks2 + 1u;
    tf_round(x0,x1,17); tf_round(x0,x1,29); tf_round(x0,x1,16); tf_round(x0,x1,24);
    x0 += ks2; x1 += ks0 + 2u;
    tf_round(x0,x1,13); tf_round(x0,x1,15); tf_round(x0,x1,26); tf_round(x0,x1,6);
    x0 += ks0; x1 += ks1 + 3u;
    tf_round(x0,x1,17); tf_round(x0,x1,29); tf_round(x0,x1,16); tf_round(x0,x1,24);
    x0 += ks1; x1 += ks2 + 4u;
    tf_round(x0,x1,13); tf_round(x0,x1,15); tf_round(x0,x1,26); tf_round(x0,x1,6);
    x0 += ks2; x1 += ks0 + 5u;
    const unsigned bits = x0 ^ x1;
    const float kp = 1.0f - *p_dropout;
    const float u  = __uint_as_float((bits >> 9) | 0x3f800000u) - 1.0f;
    const unsigned ballot = __ballot_sync(0xffffffffu, u < kp);
    if ((threadIdx.x & 31u) == 0u) g_mask[idx >> 5] = ballot;
}

// ---------------------------------------------------------------------------
// Packed fp32 helpers (Blackwell f32x2 pipe)
// ---------------------------------------------------------------------------
__device__ __forceinline__ ull pack2(float lo, float hi) {
    ull r; asm("mov.b64 %0, {%1, %2};" : "=l"(r) : "f"(lo), "f"(hi)); return r;
}
__device__ __forceinline__ void unpack2(ull v, float &lo, float &hi) {
    asm("mov.b64 {%0, %1}, %2;" : "=f"(lo), "=f"(hi) : "l"(v));
}
__device__ __forceinline__ void ffma2(ull &acc, ull a, ull b) {
    asm("fma.rn.f32x2 %0, %1, %2, %0;" : "+l"(acc) : "l"(a), "l"(b));
}
__device__ __forceinline__ void fmul2(ull &d, ull a) {
    asm("mul.rn.f32x2 %0, %0, %1;" : "+l"(d) : "l"(a));
}

// column permutation: logical col c -> physical slot, so that the pair-of-cols
// owned by (tx, pair p) sits at phys = p*32 + 2*tx (+e): lane-contiguous LDS.64
__device__ __forceinline__ int permc(int c) {
    return ((c & 7) >> 1) * 32 + (c >> 3) * 2 + (c & 1);
}

// ---------------------------------------------------------------------------
// Flash attention, BQ=BK=128, 256 threads, 8x8 micro-tiles, f32x2 FMA.
// ---------------------------------------------------------------------------
__global__ void __launch_bounds__(256, 1) attn_kernel(
    const float* __restrict__ Q, const float* __restrict__ K,
    const float* __restrict__ V, const float* __restrict__ inv_scale,
    const float* __restrict__ p_dropout, float* __restrict__ Out)
{
    extern __shared__ float sm[];
    float* Qs = sm;                    // [128][QSTR]
    float* KP = Qs + 128 * QSTR;       // Kt [kk][KSTR] (perm cols) / P [row][KSTR] (perm cols)
    float* Vs = KP + 128 * KSTR;       // [128][128] perm cols
    float* rs = Vs + 128 * 128;        // [128]

    const int b     = blockIdx.y;
    const int qbase = blockIdx.x * BQ;
    const int tid   = threadIdx.x;
    const int tx    = tid & 15;        // 16 col groups (8 logical cols each)
    const int ty    = tid >> 4;        // 16 row groups (8 rows each)

    const float kp = 1.0f - *p_dropout;
    const float* Qb = Q + (size_t)(b * S_ + qbase) * D_;
    const float* Kb = K + (size_t)b * S_ * D_;
    const float* Vb = V + (size_t)b * S_ * D_;

    // ---- load Q tile (once) ----
    for (int t = tid; t < 128 * 32; t += 256) {
        const int r = t >> 5, c4 = (t & 31) << 2;
        const float4 q4 = *reinterpret_cast<const float4*>(Qb + r * D_ + c4);
        *reinterpret_cast<float4*>(Qs + r * QSTR + c4) = q4;
    }
    if (tid < 128) rs[tid] = 1.0f / inv_scale[(size_t)b * S_ + qbase + tid];

    ull O2[8][4];
    float mrun[8], Zrun[8];
#pragma unroll
    for (int i = 0; i < 8; i++) {
        mrun[i] = -1e30f; Zrun[i] = 0.0f;
#pragma unroll
        for (int v = 0; v < 4; v++) O2[i][v] = 0ull;
    }

    unsigned wbase[8];
#pragma unroll
    for (int i = 0; i < 8; i++)
        wbase[i] = (unsigned)(b * S_ + qbase + 8 * ty + i) * (S_ / 32);
    const unsigned wword = (unsigned)(tx >> 2);      // which 32-bit word inside 128 cols
    const unsigned wshift = (unsigned)(8 * (tx & 3));

    for (int kb = 0; kb < NIT; kb++) {
        __syncthreads();   // prev PV done: KP (P) and Vs reusable

        // ---- load K transposed+permuted, V permuted ----
        const float* Kt = Kb + (size_t)kb * BK * D_;
        const float* Vt = Vb + (size_t)kb * BK * D_;
        for (int t = tid; t < 128 * 32; t += 256) {
            const int r = t >> 5, c4 = (t & 31) << 2;
            const float4 k4 = *reinterpret_cast<const float4*>(Kt + r * D_ + c4);
            const int pc = permc(r);
            KP[(c4 + 0) * KSTR + pc] = k4.x;
            KP[(c4 + 1) * KSTR + pc] = k4.y;
            KP[(c4 + 2) * KSTR + pc] = k4.z;
            KP[(c4 + 3) * KSTR + pc] = k4.w;
            const float4 v4 = *reinterpret_cast<const float4*>(Vt + r * D_ + c4);
            float* vr = Vs + r * 128;
            vr[permc(c4 + 0)] = v4.x;
            vr[permc(c4 + 1)] = v4.y;
            vr[permc(c4 + 2)] = v4.z;
            vr[permc(c4 + 3)] = v4.w;
        }
        __syncthreads();

        // ---- QK: acc2[8 rows][4 col-pairs] ----
        ull acc[8][4];
#pragma unroll
        for (int i = 0; i < 8; i++)
#pragma unroll
            for (int p = 0; p < 4; p++) acc[i][p] = 0ull;

        const float* qp = Qs + 8 * ty * QSTR;
        const float* kr = KP + 2 * tx;
#pragma unroll 4
        for (int kk = 0; kk < 128; kk++) {
            const float* krow = kr + kk * KSTR;
            const ull b0 = *reinterpret_cast<const ull*>(krow);
            const ull b1 = *reinterpret_cast<const ull*>(krow + 32);
            const ull b2 = *reinterpret_cast<const ull*>(krow + 64);
            const ull b3 = *reinterpret_cast<const ull*>(krow + 96);
#pragma unroll
            for (int i = 0; i < 8; i++) {
                const float a = qp[i * QSTR + kk];
                const ull a2 = pack2(a, a);
                ffma2(acc[i][0], a2, b0);
                ffma2(acc[i][1], a2, b1);
                ffma2(acc[i][2], a2, b2);
                ffma2(acc[i][3], a2, b3);
            }
        }
        __syncthreads();   // K reads done -> KP reusable as P

        // ---- softmax + dropout + write P (permuted cols) ----
        const unsigned woff = (unsigned)(kb * 4) + wword;
#pragma unroll
        for (int i = 0; i < 8; i++) {
            float s[8];
            unpack2(acc[i][0], s[0], s[1]);
            unpack2(acc[i][1], s[2], s[3]);
            unpack2(acc[i][2], s[4], s[5]);
            unpack2(acc[i][3], s[6], s[7]);
            const float rsc = rs[8 * ty + i];
#pragma unroll
            for (int j = 0; j < 8; j++) s[j] *= rsc;

            float mx = fmaxf(fmaxf(fmaxf(s[0], s[1]), fmaxf(s[2], s[3])),
                             fmaxf(fmaxf(s[4], s[5]), fmaxf(s[6], s[7])));
            mx = fmaxf(mx, __shfl_xor_sync(0xffffffffu, mx, 1));
            mx = fmaxf(mx, __shfl_xor_sync(0xffffffffu, mx, 2));
            mx = fmaxf(mx, __shfl_xor_sync(0xffffffffu, mx, 4));
            mx = fmaxf(mx, __shfl_xor_sync(0xffffffffu, mx, 8));

            const float mn    = fmaxf(mrun[i], mx);
            const float alpha = __expf(mrun[i] - mn);
            mrun[i] = mn;

            float p[8];
#pragma unroll
            for (int j = 0; j < 8; j++) p[j] = __expf(s[j] - mn);
            float rsum = ((p[0] + p[1]) + (p[2] + p[3])) + ((p[4] + p[5]) + (p[6] + p[7]));
            rsum += __shfl_xor_sync(0xffffffffu, rsum, 1);
            rsum += __shfl_xor_sync(0xffffffffu, rsum, 2);
            rsum += __shfl_xor_sync(0xffffffffu, rsum, 4);
            rsum += __shfl_xor_sync(0xffffffffu, rsum, 8);
            Zrun[i] = Zrun[i] * alpha + rsum;

            const ull al2 = pack2(alpha, alpha);
#pragma unroll
            for (int v = 0; v < 4; v++) fmul2(O2[i][v], al2);

            const unsigned mw = g_mask[wbase[i] + woff];
            const unsigned mb = (mw >> wshift) & 0xffu;
#pragma unroll
            for (int j = 0; j < 8; j++)
                if (!((mb >> j) & 1u)) p[j] = 0.0f;

            float* prow = KP + (8 * ty + i) * KSTR + 2 * tx;
            *reinterpret_cast<ull*>(prow)      = pack2(p[0], p[1]);
            *reinterpret_cast<ull*>(prow + 32) = pack2(p[2], p[3]);
            *reinterpret_cast<ull*>(prow + 64) = pack2(p[4], p[5]);
            *reinterpret_cast<ull*>(prow + 96) = pack2(p[6], p[7]);
        }
        __syncthreads();

        // ---- PV: O2 += P * V  (iterate physical pair slots) ----
        const float* pvP = KP + 8 * ty * KSTR;
#pragma unroll
        for (int pp = 0; pp < 4; pp++) {
#pragma unroll 4
            for (int t = 0; t < 16; t++) {
                const int ph = pp * 32 + t * 2;         // P physical offset (pair)
                const int c0 = t * 8 + pp * 2;          // logical key rows c0, c0+1
                const float* v0 = Vs + c0 * 128 + 2 * tx;
                const float* v1 = v0 + 128;
                ull vb0[4], vb1[4];
#pragma unroll
                for (int v = 0; v < 4; v++) {
                    vb0[v] = *reinterpret_cast<const ull*>(v0 + v * 32);
                    vb1[v] = *reinterpret_cast<const ull*>(v1 + v * 32);
                }
#pragma unroll
                for (int i = 0; i < 8; i++) {
                    const ull pp2 = *reinterpret_cast<const ull*>(pvP + i * KSTR + ph);
                    float f0, f1; unpack2(pp2, f0, f1);
                    const ull d0 = pack2(f0, f0), d1 = pack2(f1, f1);
                    ffma2(O2[i][0], d0, vb0[0]); ffma2(O2[i][1], d0, vb0[1]);
                    ffma2(O2[i][2], d0, vb0[2]); ffma2(O2[i][3], d0, vb0[3]);
                    ffma2(O2[i][0], d1, vb1[0]); ffma2(O2[i][1], d1, vb1[1]);
                    ffma2(O2[i][2], d1, vb1[2]); ffma2(O2[i][3], d1, vb1[3]);
                }
            }
        }
    }

    // ---- epilogue: out = O / (Z * keep_prob); logical col = 8tx + 2v + e ----
#pragma unroll
    for (int i = 0; i < 8; i++) {
        const float inv = 1.0f / (Zrun[i] * kp);
        float o[8];
        unpack2(O2[i][0], o[0], o[1]);
        unpack2(O2[i][1], o[2], o[3]);
        unpack2(O2[i][2], o[4], o[5]);
        unpack2(O2[i][3], o[6], o[7]);
        float* orow = Out + (size_t)(b * S_ + qbase + 8 * ty + i) * D_ + 8 * tx;
        float4 w0 = make_float4(o[0] * inv, o[1] * inv, o[2] * inv, o[3] * inv);
        float4 w1 = make_float4(o[4] * inv, o[5] * inv, o[6] * inv, o[7] * inv);
        *reinterpret_cast<float4*>(orow)     = w0;
        *reinterpret_cast<float4*>(orow + 4) = w1;
    }
}

// ---------------------------------------------------------------------------
// Launch
// ---------------------------------------------------------------------------
extern "C" void kernel_launch(void* const* d_in, const int* in_sizes, int n_in,
                              void* d_out, int out_size) {
    const float* Q   = (const float*)d_in[0];
    const float* K   = (const float*)d_in[1];
    const float* V   = (const float*)d_in[2];
    const float* isf = (const float*)d_in[3];
    const float* dp  = (const float*)d_in[4];
    float* Out = (float*)d_out;

    constexpr int SMEM_BYTES =
        (128 * QSTR + 128 * KSTR + 128 * 128 + 128) * (int)sizeof(float);
    cudaFuncSetAttribute(attn_kernel,
                         cudaFuncAttributeMaxDynamicSharedMemorySize, SMEM_BYTES);

    mask_kernel<<<(1u << 26) / 256, 256>>>(dp);

    dim3 grid(S_ / BQ, B_);
    attn_kernel<<<grid, 256, SMEM_BYTES>>>(Q, K, V, isf, dp, Out);
}

// round 3
// speedup vs baseline: 1.3109x; 1.0099x over previous
#include <cuda_runtime.h>
#include <cstdint>

typedef unsigned long long ull;

// ---------------------------------------------------------------------------
// Problem constants
// ---------------------------------------------------------------------------
constexpr int B_ = 16, S_ = 2048, D_ = 128;
constexpr int BQ = 128, BK = 128;
constexpr int QSTR = 132;           // Qs row stride (floats), even (LDS.64-able)
constexpr int KSTR = 130;           // Kt / P row stride, even
constexpr int NIT  = S_ / BK;       // 16

// Packed dropout keep-mask: 16*2048*2048 bits = 8 MB
__device__ __align__(16) unsigned int g_mask[(1u << 26) / 32];

// ---------------------------------------------------------------------------
// Threefry-2x32 (JAX partitionable): key=(0,42), ctr=(0,idx), draw = x0^x1
// ---------------------------------------------------------------------------
__device__ __forceinline__ void tf_round(unsigned &x0, unsigned &x1, int r) {
    x0 += x1;
    x1 = __funnelshift_l(x1, x1, r);
    x1 ^= x0;
}

__global__ void __launch_bounds__(256) mask_kernel(const float* __restrict__ p_dropout) {
    const unsigned idx = blockIdx.x * 256u + threadIdx.x;
    const unsigned ks0 = 0u, ks1 = 42u, ks2 = 0x1BD11BDAu ^ 42u;
    unsigned x0 = ks0, x1 = idx + ks1;
    tf_round(x0,x1,13); tf_round(x0,x1,15); tf_round(x0,x1,26); tf_round(x0,x1,6);
    x0 += ks1; x1 += ks2 + 1u;
    tf_round(x0,x1,17); tf_round(x0,x1,29); tf_round(x0,x1,16); tf_round(x0,x1,24);
    x0 += ks2; x1 += ks0 + 2u;
    tf_round(x0,x1,13); tf_round(x0,x1,15); tf_round(x0,x1,26); tf_round(x0,x1,6);
    x0 += ks0; x1 += ks1 + 3u;
    tf_round(x0,x1,17); tf_round(x0,x1,29); tf_round(x0,x1,16); tf_round(x0,x1,24);
    x0 += ks1; x1 += ks2 + 4u;
    tf_round(x0,x1,13); tf_round(x0,x1,15); tf_round(x0,x1,26); tf_round(x0,x1,6);
    x0 += ks2; x1 += ks0 + 5u;
    const unsigned bits = x0 ^ x1;
    const float kp = 1.0f - *p_dropout;
    const float u  = __uint_as_float((bits >> 9) | 0x3f800000u) - 1.0f;
    const unsigned ballot = __ballot_sync(0xffffffffu, u < kp);
    if ((threadIdx.x & 31u) == 0u) g_mask[idx >> 5] = ballot;
}

// ---------------------------------------------------------------------------
// Packed fp32 helpers (Blackwell f32x2 pipe)
// ---------------------------------------------------------------------------
__device__ __forceinline__ ull pack2(float lo, float hi) {
    ull r; asm("mov.b64 %0, {%1, %2};" : "=l"(r) : "f"(lo), "f"(hi)); return r;
}
__device__ __forceinline__ void unpack2(ull v, float &lo, float &hi) {
    asm("mov.b64 {%0, %1}, %2;" : "=f"(lo), "=f"(hi) : "l"(v));
}
__device__ __forceinline__ void ffma2(ull &acc, ull a, ull b) {
    asm("fma.rn.f32x2 %0, %1, %2, %0;" : "+l"(acc) : "l"(a), "l"(b));
}
__device__ __forceinline__ void fmul2(ull &d, ull a) {
    asm("mul.rn.f32x2 %0, %0, %1;" : "+l"(d) : "l"(a));
}

// logical col c -> physical slot: pair p of thread tx sits at p*32 + 2*tx (+e)
// inverse: phys p*32+2t+e  <->  logical c = t*8 + p*2 + e
__device__ __forceinline__ int permc(int c) {
    return ((c & 7) >> 1) * 32 + (c >> 3) * 2 + (c & 1);
}

// ---------------------------------------------------------------------------
// Flash attention, BQ=BK=128, 512 threads, 4x8 micro-tiles, f32x2 FMA.
// ---------------------------------------------------------------------------
__global__ void __launch_bounds__(512, 1) attn_kernel(
    const float* __restrict__ Q, const float* __restrict__ K,
    const float* __restrict__ V, const float* __restrict__ inv_scale,
    const float* __restrict__ p_dropout, float* __restrict__ Out)
{
    extern __shared__ float sm[];
    float* Qs = sm;                    // [128][QSTR]
    float* KP = Qs + 128 * QSTR;       // Kt [kk][KSTR] (perm) / P [row][KSTR] (perm)
    float* Vs = KP + 128 * KSTR;       // [128][128] perm cols
    float* rs = Vs + 128 * 128;        // [128]

    const int b     = blockIdx.y;
    const int qbase = blockIdx.x * BQ;
    const int tid   = threadIdx.x;
    const int tx    = tid & 15;        // 16 col groups (8 logical cols)
    const int ty    = tid >> 4;        // 32 row groups (4 rows)

    const float kp = 1.0f - *p_dropout;
    const float* Qb = Q + (size_t)(b * S_ + qbase) * D_;
    const float* Kb = K + (size_t)b * S_ * D_;
    const float* Vb = V + (size_t)b * S_ * D_;

    // ---- load Q tile (once) ----
    for (int t = tid; t < 128 * 32; t += 512) {
        const int r = t >> 5, c4 = (t & 31) << 2;
        *reinterpret_cast<float4*>(Qs + r * QSTR + c4) =
            *reinterpret_cast<const float4*>(Qb + r * D_ + c4);
    }
    if (tid < 128) rs[tid] = 1.0f / inv_scale[(size_t)b * S_ + qbase + tid];

    ull O2[4][4];
    float mrun[4], Zrun[4];
#pragma unroll
    for (int i = 0; i < 4; i++) {
        mrun[i] = -1e30f; Zrun[i] = 0.0f;
#pragma unroll
        for (int v = 0; v < 4; v++) O2[i][v] = 0ull;
    }

    unsigned wbase[4];
#pragma unroll
    for (int i = 0; i < 4; i++)
        wbase[i] = (unsigned)(b * S_ + qbase + 4 * ty + i) * (S_ / 32);
    const unsigned wword  = (unsigned)(tx >> 2);
    const unsigned wshift = (unsigned)(8 * (tx & 3));

    for (int kb = 0; kb < NIT; kb++) {
        __syncthreads();   // prev PV done: KP and Vs reusable

        // ---- load K transposed+permuted, V permuted ----
        const float* Kt = Kb + (size_t)kb * BK * D_;
        const float* Vt = Vb + (size_t)kb * BK * D_;
        for (int t = tid; t < 128 * 32; t += 512) {
            const int r = t >> 5, c4 = (t & 31) << 2;
            const float4 k4 = *reinterpret_cast<const float4*>(Kt + r * D_ + c4);
            const int pc = permc(r);
            KP[(c4 + 0) * KSTR + pc] = k4.x;
            KP[(c4 + 1) * KSTR + pc] = k4.y;
            KP[(c4 + 2) * KSTR + pc] = k4.z;
            KP[(c4 + 3) * KSTR + pc] = k4.w;
            const float4 v4 = *reinterpret_cast<const float4*>(Vt + r * D_ + c4);
            float* vr = Vs + r * 128;
            vr[permc(c4 + 0)] = v4.x;
            vr[permc(c4 + 1)] = v4.y;
            vr[permc(c4 + 2)] = v4.z;
            vr[permc(c4 + 3)] = v4.w;
        }
        __syncthreads();

        // ---- QK: acc[4 rows][4 col-pairs], kk unrolled by 2 ----
        ull acc[4][4];
#pragma unroll
        for (int i = 0; i < 4; i++)
#pragma unroll
            for (int p = 0; p < 4; p++) acc[i][p] = 0ull;

        const float* qp = Qs + 4 * ty * QSTR;
        const float* kr = KP + 2 * tx;
#pragma unroll 4
        for (int kk = 0; kk < 128; kk += 2) {
            const float* k0 = kr + kk * KSTR;
            const float* k1 = k0 + KSTR;
            const ull b00 = *reinterpret_cast<const ull*>(k0);
            const ull b01 = *reinterpret_cast<const ull*>(k0 + 32);
            const ull b02 = *reinterpret_cast<const ull*>(k0 + 64);
            const ull b03 = *reinterpret_cast<const ull*>(k0 + 96);
            const ull b10 = *reinterpret_cast<const ull*>(k1);
            const ull b11 = *reinterpret_cast<const ull*>(k1 + 32);
            const ull b12 = *reinterpret_cast<const ull*>(k1 + 64);
            const ull b13 = *reinterpret_cast<const ull*>(k1 + 96);
#pragma unroll
            for (int i = 0; i < 4; i++) {
                const ull q2 = *reinterpret_cast<const ull*>(qp + i * QSTR + kk);
                float qa, qb; unpack2(q2, qa, qb);
                const ull a0 = pack2(qa, qa);
                const ull a1 = pack2(qb, qb);
                ffma2(acc[i][0], a0, b00); ffma2(acc[i][1], a0, b01);
                ffma2(acc[i][2], a0, b02); ffma2(acc[i][3], a0, b03);
                ffma2(acc[i][0], a1, b10); ffma2(acc[i][1], a1, b11);
                ffma2(acc[i][2], a1, b12); ffma2(acc[i][3], a1, b13);
            }
        }
        __syncthreads();   // K reads done -> KP reusable as P

        // ---- softmax + dropout + write P (permuted cols) ----
        const unsigned woff = (unsigned)(kb * 4) + wword;
#pragma unroll
        for (int i = 0; i < 4; i++) {
            float s[8];
            unpack2(acc[i][0], s[0], s[1]);
            unpack2(acc[i][1], s[2], s[3]);
            unpack2(acc[i][2], s[4], s[5]);
            unpack2(acc[i][3], s[6], s[7]);
            const float rsc = rs[4 * ty + i];
#pragma unroll
            for (int j = 0; j < 8; j++) s[j] *= rsc;

            float mx = fmaxf(fmaxf(fmaxf(s[0], s[1]), fmaxf(s[2], s[3])),
                             fmaxf(fmaxf(s[4], s[5]), fmaxf(s[6], s[7])));
            mx = fmaxf(mx, __shfl_xor_sync(0xffffffffu, mx, 1));
            mx = fmaxf(mx, __shfl_xor_sync(0xffffffffu, mx, 2));
            mx = fmaxf(mx, __shfl_xor_sync(0xffffffffu, mx, 4));
            mx = fmaxf(mx, __shfl_xor_sync(0xffffffffu, mx, 8));

            const float mn    = fmaxf(mrun[i], mx);
            const float alpha = __expf(mrun[i] - mn);
            mrun[i] = mn;

            float p[8];
#pragma unroll
            for (int j = 0; j < 8; j++) p[j] = __expf(s[j] - mn);
            float rsum = ((p[0] + p[1]) + (p[2] + p[3])) + ((p[4] + p[5]) + (p[6] + p[7]));
            rsum += __shfl_xor_sync(0xffffffffu, rsum, 1);
            rsum += __shfl_xor_sync(0xffffffffu, rsum, 2);
            rsum += __shfl_xor_sync(0xffffffffu, rsum, 4);
            rsum += __shfl_xor_sync(0xffffffffu, rsum, 8);
            Zrun[i] = Zrun[i] * alpha + rsum;

            const ull al2 = pack2(alpha, alpha);
#pragma unroll
            for (int v = 0; v < 4; v++) fmul2(O2[i][v], al2);

            const unsigned mw = g_mask[wbase[i] + woff];
            const unsigned mb = (mw >> wshift) & 0xffu;
#pragma unroll
            for (int j = 0; j < 8; j++)
                if (!((mb >> j) & 1u)) p[j] = 0.0f;

            float* prow = KP + (4 * ty + i) * KSTR + 2 * tx;
            *reinterpret_cast<ull*>(prow)      = pack2(p[0], p[1]);
            *reinterpret_cast<ull*>(prow + 32) = pack2(p[2], p[3]);
            *reinterpret_cast<ull*>(prow + 64) = pack2(p[4], p[5]);
            *reinterpret_cast<ull*>(prow + 96) = pack2(p[6], p[7]);
        }
        __syncthreads();

        // ---- PV: O2 += P * V ----
        const float* pvP = KP + 4 * ty * KSTR;
#pragma unroll
        for (int pp = 0; pp < 4; pp++) {
#pragma unroll 4
            for (int t = 0; t < 16; t++) {
                const int ph = pp * 32 + t * 2;   // P physical pair offset
                const int c0 = t * 8 + pp * 2;    // logical key rows c0, c0+1
                const float* v0 = Vs + c0 * 128 + 2 * tx;
                const float* v1 = v0 + 128;
                ull vb0[4], vb1[4];
#pragma unroll
                for (int v = 0; v < 4; v++) {
                    vb0[v] = *reinterpret_cast<const ull*>(v0 + v * 32);
                    vb1[v] = *reinterpret_cast<const ull*>(v1 + v * 32);
                }
#pragma unroll
                for (int i = 0; i < 4; i++) {
                    const ull pp2 = *reinterpret_cast<const ull*>(pvP + i * KSTR + ph);
                    float f0, f1; unpack2(pp2, f0, f1);
                    const ull d0 = pack2(f0, f0), d1 = pack2(f1, f1);
                    ffma2(O2[i][0], d0, vb0[0]); ffma2(O2[i][1], d0, vb0[1]);
                    ffma2(O2[i][2], d0, vb0[2]); ffma2(O2[i][3], d0, vb0[3]);
                    ffma2(O2[i][0], d1, vb1[0]); ffma2(O2[i][1], d1, vb1[1]);
                    ffma2(O2[i][2], d1, vb1[2]); ffma2(O2[i][3], d1, vb1[3]);
                }
            }
        }
    }

    // ---- epilogue: out = O / (Z * keep_prob); logical col = 8tx + 2v + e ----
#pragma unroll
    for (int i = 0; i < 4; i++) {
        const float inv = 1.0f / (Zrun[i] * kp);
        float o[8];
        unpack2(O2[i][0], o[0], o[1]);
        unpack2(O2[i][1], o[2], o[3]);
        unpack2(O2[i][2], o[4], o[5]);
        unpack2(O2[i][3], o[6], o[7]);
        float* orow = Out + (size_t)(b * S_ + qbase + 4 * ty + i) * D_ + 8 * tx;
        *reinterpret_cast<float4*>(orow) =
            make_float4(o[0] * inv, o[1] * inv, o[2] * inv, o[3] * inv);
        *reinterpret_cast<float4*>(orow + 4) =
            make_float4(o[4] * inv, o[5] * inv, o[6] * inv, o[7] * inv);
    }
}

// ---------------------------------------------------------------------------
// Launch
// ---------------------------------------------------------------------------
extern "C" void kernel_launch(void* const* d_in, const int* in_sizes, int n_in,
                              void* d_out, int out_size) {
    const float* Q   = (const float*)d_in[0];
    const float* K   = (const float*)d_in[1];
    const float* V   = (const float*)d_in[2];
    const float* isf = (const float*)d_in[3];
    const float* dp  = (const float*)d_in[4];
    float* Out = (float*)d_out;

    constexpr int SMEM_BYTES =
        (128 * QSTR + 128 * KSTR + 128 * 128 + 128) * (int)sizeof(float);
    cudaFuncSetAttribute(attn_kernel,
                         cudaFuncAttributeMaxDynamicSharedMemorySize, SMEM_BYTES);

    mask_kernel<<<(1u << 26) / 256, 256>>>(dp);

    dim3 grid(S_ / BQ, B_);
    attn_kernel<<<grid, 512, SMEM_BYTES>>>(Q, K, V, isf, dp, Out);
}